// round 16
// baseline (speedup 1.0000x reference)
#include <cuda_runtime.h>

// SMFNet: out[i,:] = relu(X@Wf^T)[i,0]*V[i,:] + [i,1]*V[(i+1)%N,:],  V = relu(X@Wg^T)
// Thread-per-row via smem staging: no cross-lane reductions.

#define THREADS 128
#define TILE    128
#define RV      33                      // row stride in float4 (32 + 1 pad)
#define SX_F4   ((TILE + 1) * RV)       // 129 * 33 = 4257 float4
#define SW_F4   128                     // wf0,wf1,wg0,wg1 (32 float4 each)
#define SMEM_BYTES ((SX_F4 + SW_F4) * 16 + (TILE + 2) * 8)

__global__ void __launch_bounds__(THREADS)
smfnet_kernel(const float4* __restrict__ X,
              const float4* __restrict__ Wf,
              const float4* __restrict__ Wg,
              float2* __restrict__ out, int N)
{
    extern __shared__ float4 sm[];
    float4* sX = sm;                         // [TILE+1][RV]
    float4* sW = sm + SX_F4;                 // [128]
    float2* sV = (float2*)(sW + SW_F4);      // [TILE+1]

    const int t = threadIdx.x;
    const long long r0 = (long long)blockIdx.x * TILE;
    const int nrows = (int)min((long long)TILE, (long long)N - r0);

    // Stage weights (2 KB): sW[0..63]=Wf rows 0,1 ; sW[64..127]=Wg rows 0,1
    if (t < 64)  sW[t] = Wf[t];
    else         sW[t] = Wg[t - 64];

    // Stage X rows [r0, r0+nrows) plus wrapped boundary row (r0+nrows)%N.
    const int total = (nrows + 1) * 32;
    for (int idx = t; idx < total; idx += THREADS) {
        const int r = idx >> 5, c = idx & 31;
        long long g = r0 + r;
        if (r == nrows) g = (r0 + nrows) % (long long)N;
        sX[r * RV + c] = X[g * 32 + c];
    }
    __syncthreads();

    float f0 = 0.f, f1 = 0.f;
    if (t < nrows) {
        float g0 = 0.f, g1 = 0.f;
        const float4* xr = sX + t * RV;
        #pragma unroll 4
        for (int j = 0; j < 32; j++) {
            const float4 x = xr[j];
            const float4 a = sW[j];
            const float4 b = sW[32 + j];
            const float4 c = sW[64 + j];
            const float4 d = sW[96 + j];
            f0 = fmaf(x.x, a.x, fmaf(x.y, a.y, fmaf(x.z, a.z, fmaf(x.w, a.w, f0))));
            f1 = fmaf(x.x, b.x, fmaf(x.y, b.y, fmaf(x.z, b.z, fmaf(x.w, b.w, f1))));
            g0 = fmaf(x.x, c.x, fmaf(x.y, c.y, fmaf(x.z, c.z, fmaf(x.w, c.w, g0))));
            g1 = fmaf(x.x, d.x, fmaf(x.y, d.y, fmaf(x.z, d.z, fmaf(x.w, d.w, g1))));
        }
        f0 = fmaxf(f0, 0.f);
        f1 = fmaxf(f1, 0.f);
        sV[t] = make_float2(fmaxf(g0, 0.f), fmaxf(g1, 0.f));

        if (t == nrows - 1) {
            // Wrapped boundary row: only V (Wg dots) needed.
            float e0 = 0.f, e1 = 0.f;
            const float4* xe = sX + nrows * RV;
            #pragma unroll 4
            for (int j = 0; j < 32; j++) {
                const float4 x = xe[j];
                const float4 c = sW[64 + j];
                const float4 d = sW[96 + j];
                e0 = fmaf(x.x, c.x, fmaf(x.y, c.y, fmaf(x.z, c.z, fmaf(x.w, c.w, e0))));
                e1 = fmaf(x.x, d.x, fmaf(x.y, d.y, fmaf(x.z, d.z, fmaf(x.w, d.w, e1))));
            }
            sV[nrows] = make_float2(fmaxf(e0, 0.f), fmaxf(e1, 0.f));
        }
    }
    __syncthreads();

    if (t < nrows) {
        const float2 v  = sV[t];
        const float2 vn = sV[t + 1];
        out[r0 + t] = make_float2(fmaf(f0, v.x, f1 * vn.x),
                                  fmaf(f0, v.y, f1 * vn.y));
    }
}

extern "C" void kernel_launch(void* const* d_in, const int* in_sizes, int n_in,
                              void* d_out, int out_size) {
    const float4* X  = (const float4*)d_in[0];   // [N,128] fp32
    const float4* Wf = (const float4*)d_in[1];   // [2,128] fp32
    const float4* Wg = (const float4*)d_in[2];   // [2,128] fp32
    float2* out = (float2*)d_out;                // [N,2] fp32

    const int N = in_sizes[0] / 128;
    const int grid = (N + TILE - 1) / TILE;

    static bool attr_set = false;
    if (!attr_set) {
        cudaFuncSetAttribute(smfnet_kernel,
                             cudaFuncAttributeMaxDynamicSharedMemorySize,
                             SMEM_BYTES);
        attr_set = true;
    }

    smfnet_kernel<<<grid, THREADS, SMEM_BYTES>>>(X, Wf, Wg, out, N);
}

// round 17
// speedup vs baseline: 2.6599x; 2.6599x over previous
#include <cuda_runtime.h>

// SMFNet: out[i,:] = F[i,0]*V[i] + F[i,1]*V[(i+1)%N],  V=relu(X@Wg^T), F=relu(X@Wf^T)
// Warp-per-row (32 lanes x float4 = 512B coalesced), 32 warps/block, 4 rows/warp.
// Merged 4-value warp reduction: 7 SHFL/row instead of 20.

#define WARPS_PER_BLOCK 32
#define ROWS_PER_WARP   4
#define ROWS_PER_BLOCK  (WARPS_PER_BLOCK * ROWS_PER_WARP)  // 128
#define D_VEC           32                                  // 128 floats = 32 float4

__device__ __forceinline__ float dot4(float4 a, float4 b) {
    return fmaf(a.x, b.x, fmaf(a.y, b.y, fmaf(a.z, b.z, a.w * b.w)));
}

// Merge two independent reductions into one stream:
// lanes with (lane & mask)==0 carry a-partials, ==1 carry b-partials.
__device__ __forceinline__ float merge_red(float a, float b, int mask, int lane) {
    const bool hi = (lane & mask) != 0;
    const float keep = hi ? b : a;
    const float send = hi ? a : b;
    return keep + __shfl_xor_sync(0xffffffffu, send, mask);
}

__global__ __launch_bounds__(1024, 1)
void smfnet_kernel(const float4* __restrict__ X,
                   const float4* __restrict__ Wf,
                   const float4* __restrict__ Wg,
                   float2* __restrict__ out,
                   int N) {
    __shared__ float2 sV[ROWS_PER_BLOCK + 1];

    const int tid  = threadIdx.x;
    const int wid  = tid >> 5;
    const int lane = tid & 31;

    // Per-lane weight slices: lane l holds elements [4l, 4l+4).
    const float4 wf0 = Wf[lane];
    const float4 wf1 = Wf[D_VEC + lane];
    const float4 wg0 = Wg[lane];
    const float4 wg1 = Wg[D_VEC + lane];

    const long long r0 = (long long)blockIdx.x * ROWS_PER_BLOCK;
    const int nrows = (int)min((long long)ROWS_PER_BLOCK, (long long)N - r0);

    const int base_lr = wid * ROWS_PER_WARP;

    // Issue all row loads up front (MLP=4 per warp).
    float4 xv[ROWS_PER_WARP];
    #pragma unroll
    for (int it = 0; it < ROWS_PER_WARP; it++) {
        const int lr = base_lr + it;
        if (lr < nrows)
            xv[it] = X[(r0 + lr) * D_VEC + lane];
    }

    float f0[ROWS_PER_WARP], f1[ROWS_PER_WARP];

    #pragma unroll
    for (int it = 0; it < ROWS_PER_WARP; it++) {
        const int lr = base_lr + it;
        if (lr >= nrows) continue;   // warp-uniform

        const float pf0 = dot4(xv[it], wf0);
        const float pf1 = dot4(xv[it], wf1);
        const float pg0 = dot4(xv[it], wg0);
        const float pg1 = dot4(xv[it], wg1);

        // Merged reduction: 6 shuffles for all four sums.
        float m1 = merge_red(pf0, pf1, 1, lane);   // bit0: 0->f0, 1->f1
        float m2 = merge_red(pg0, pg1, 1, lane);   // bit0: 0->g0, 1->g1
        float m  = merge_red(m1,  m2,  2, lane);   // lane&3: 0 f0, 1 f1, 2 g0, 3 g1
        m += __shfl_xor_sync(0xffffffffu, m, 4);
        m += __shfl_xor_sync(0xffffffffu, m, 8);
        m += __shfl_xor_sync(0xffffffffu, m, 16);
        // Pair up: lane0 gets f1 (from lane1), lane2 gets g1 (from lane3).
        const float n = __shfl_xor_sync(0xffffffffu, m, 1);

        f0[it] = fmaxf(m, 0.0f);   // valid on lane 0
        f1[it] = fmaxf(n, 0.0f);
        if (lane == 2)
            sV[lr] = make_float2(fmaxf(m, 0.0f), fmaxf(n, 0.0f));
    }

    // Extra wrapped boundary row: only V needed.
    if (wid == 0) {
        long long rext = r0 + nrows;
        if (rext >= N) rext -= N;
        const float4 xe = X[rext * D_VEC + lane];
        const float pg0 = dot4(xe, wg0);
        const float pg1 = dot4(xe, wg1);
        float m = merge_red(pg0, pg1, 1, lane);    // bit0: 0->g0, 1->g1
        m += __shfl_xor_sync(0xffffffffu, m, 2);
        m += __shfl_xor_sync(0xffffffffu, m, 4);
        m += __shfl_xor_sync(0xffffffffu, m, 8);
        m += __shfl_xor_sync(0xffffffffu, m, 16);
        const float n = __shfl_xor_sync(0xffffffffu, m, 1);
        if (lane == 0)
            sV[nrows] = make_float2(fmaxf(m, 0.0f), fmaxf(n, 0.0f));
    }

    __syncthreads();

    #pragma unroll
    for (int it = 0; it < ROWS_PER_WARP; it++) {
        const int lr = base_lr + it;
        if (lr < nrows && lane == 0) {
            const float2 v  = sV[lr];
            const float2 vn = sV[lr + 1];
            out[r0 + lr] = make_float2(fmaf(f0[it], v.x, f1[it] * vn.x),
                                       fmaf(f0[it], v.y, f1[it] * vn.y));
        }
    }
}

extern "C" void kernel_launch(void* const* d_in, const int* in_sizes, int n_in,
                              void* d_out, int out_size) {
    const float4* X  = (const float4*)d_in[0];   // [N,128] fp32
    const float4* Wf = (const float4*)d_in[1];   // [2,128] fp32
    const float4* Wg = (const float4*)d_in[2];   // [2,128] fp32
    float2* out = (float2*)d_out;                // [N,2] fp32

    const int N = in_sizes[0] / 128;
    const int grid = (N + ROWS_PER_BLOCK - 1) / ROWS_PER_BLOCK;

    smfnet_kernel<<<grid, WARPS_PER_BLOCK * 32>>>(X, Wf, Wg, out, N);
}